// round 10
// baseline (speedup 1.0000x reference)
#include <cuda_runtime.h>
#include <cuda_fp16.h>
#include <cstdint>

// ============================================================================
// QuantizedLinear: out = scale * (x @ S^T) + bias, S = sign(w)*(|w|>0.7*mean|w|)
// x [65536, 512] fp32, w [512, 512] fp32, bias [512] fp32, out [65536, 512] fp32
//
// R10: GEMM is at the legacy fp16 mma.sync floor (~120us). Remove the separate
// x->fp16 pass by fusing conversion into the GEMM A-path:
//   A: LDG fp32 -> cvt.rn.f16x2 -> STS fp16 (SW128), double-buffered
//   B: cp.async fp16 ternary (SW128)
// Fragments via ldmatrix.x4; mma.sync.m16n8k16.f16. (compute_103: no tcgen05.)
// ============================================================================
#define K_DIM 512
#define N_DIM 512
#define BM 128
#define BN 64
#define BK 64
#define KT (K_DIM / BK)      // 8
#define THREADS 256

#define A_STAGE_BYTES (BM * BK * 2)                    // 16384 (128B rows, SW128)
#define B_STAGE_BYTES (BN * BK * 2)                    // 8192
#define STAGE_BYTES   (A_STAGE_BYTES + B_STAGE_BYTES)  // 24576
#define SMEM_TOTAL    (2 * STAGE_BYTES + 128)          // 49280

// Scratch (allocation-free __device__ globals)
__device__ __half  d_wq[N_DIM * K_DIM];
__device__ double  d_partial[256];
__device__ float   d_scale;
__device__ float   d_thresh;

// ============================================================================
// Prep kernels
// ============================================================================
__global__ void k_abssum(const float* __restrict__ w) {
    __shared__ double s[256];
    int b = blockIdx.x, t = threadIdx.x;
    const float* p = w + b * 1024;
    double acc = (double)fabsf(p[t]) + (double)fabsf(p[t + 256]) +
                 (double)fabsf(p[t + 512]) + (double)fabsf(p[t + 768]);
    s[t] = acc;
    __syncthreads();
    for (int o = 128; o > 0; o >>= 1) {
        if (t < o) s[t] += s[t + o];
        __syncthreads();
    }
    if (t == 0) d_partial[b] = s[0];
}

__global__ void k_scale() {
    double tot = 0.0;
    for (int i = 0; i < 256; i++) tot += d_partial[i];
    float sc = (float)(tot / (double)(N_DIM * K_DIM));
    if (sc < 1e-8f) sc = 1e-8f;
    d_scale = sc;
    d_thresh = 0.7f * sc;
}

__global__ void k_quant(const float* __restrict__ w) {
    int i = blockIdx.x * blockDim.x + threadIdx.x;
    float v = w[i];
    float th = d_thresh;
    float q = (fabsf(v) > th) ? (v > 0.0f ? 1.0f : -1.0f) : 0.0f;
    d_wq[i] = __float2half_rn(q);    // exact in fp16
}

// ============================================================================
// Helpers
// ============================================================================
__device__ __forceinline__ uint32_t smem_u32(const void* p) {
    uint32_t a;
    asm("{ .reg .u64 t; cvta.to.shared.u64 t, %1; cvt.u32.u64 %0, t; }"
        : "=r"(a) : "l"(p));
    return a;
}

__device__ __forceinline__ void cp16(uint32_t saddr, const void* gaddr) {
    asm volatile("cp.async.cg.shared.global [%0], [%1], 16;"
                 :: "r"(saddr), "l"(gaddr) : "memory");
}

__device__ __forceinline__ void cp_commit() {
    asm volatile("cp.async.commit_group;" ::: "memory");
}

__device__ __forceinline__ void cp_wait0() {
    asm volatile("cp.async.wait_group 0;" ::: "memory");
}

__device__ __forceinline__ uint32_t pack_h2(float lo, float hi) {
    uint32_t r;
    asm("cvt.rn.f16x2.f32 %0, %1, %2;" : "=r"(r) : "f"(hi), "f"(lo));
    return r;
}

__device__ __forceinline__ void sts128(uint32_t addr, uint32_t r0, uint32_t r1,
                                       uint32_t r2, uint32_t r3) {
    asm volatile("st.shared.v4.b32 [%0], {%1,%2,%3,%4};"
                 :: "r"(addr), "r"(r0), "r"(r1), "r"(r2), "r"(r3) : "memory");
}

__device__ __forceinline__ void ldsm_x4(uint32_t& r0, uint32_t& r1,
                                        uint32_t& r2, uint32_t& r3,
                                        uint32_t addr) {
    asm volatile("ldmatrix.sync.aligned.m8n8.x4.shared.b16 {%0,%1,%2,%3}, [%4];"
                 : "=r"(r0), "=r"(r1), "=r"(r2), "=r"(r3) : "r"(addr));
}

__device__ __forceinline__ void mma_f16(float* c, uint32_t a0, uint32_t a1,
                                        uint32_t a2, uint32_t a3,
                                        uint32_t b0, uint32_t b1) {
    asm volatile(
        "mma.sync.aligned.m16n8k16.row.col.f32.f16.f16.f32 "
        "{%0,%1,%2,%3}, {%4,%5,%6,%7}, {%8,%9}, {%0,%1,%2,%3};"
        : "+f"(c[0]), "+f"(c[1]), "+f"(c[2]), "+f"(c[3])
        : "r"(a0), "r"(a1), "r"(a2), "r"(a3), "r"(b0), "r"(b1));
}

// ============================================================================
// Main GEMM: block 128x64, 8 warps (4M x 2N), warp tile 32x32
// A: LDG fp32 + cvt + STS fp16 (SW128); B: cp.async fp16 (SW128)
// SW128: 128B rows, 16B chunk c stored at position c ^ (row & 7).
// ============================================================================
__global__ void __launch_bounds__(THREADS, 2) gemm_f16(
    const float* __restrict__ x,
    const float* __restrict__ bias,
    float* __restrict__ out)
{
    extern __shared__ char smem[];
    const uint32_t sb = (smem_u32(smem) + 127u) & ~127u;
    const int tid = threadIdx.x;
    const int wid = tid >> 5;
    const int lane = tid & 31;
    const int grp = lane >> 2;
    const int qc = lane & 3;

    const int ntile = blockIdx.x & 7;       // consecutive bids share M-tile
    const int mtile = blockIdx.x >> 3;
    const int m0 = mtile * BM;
    const int n0 = ntile * BN;

    const int warp_m = (wid & 3) * 32;
    const int warp_n = (wid >> 2) * 32;

    const __half* wq = d_wq;

    // ---- A staging: thread handles row = tid>>1, cols h*32..h*32+31 ----
    const int arow = tid >> 1;
    const int ah = tid & 1;
    const float* agp_base = x + (size_t)(m0 + arow) * K_DIM + ah * 32;
    // STS addresses: chunk c = 4*ah + t, position = c ^ (arow & 7)
    uint32_t asts[4];
    #pragma unroll
    for (int t = 0; t < 4; t++)
        asts[t] = (uint32_t)arow * 128 +
                  (uint32_t)(((4 * ah + t) ^ (arow & 7)) << 4);

    // ---- B loader: 512 chunks / 256 threads = 2 per thread ----
    auto load_B = [&](int s, int kt) {
        const uint32_t sB = sb + s * STAGE_BYTES + A_STAGE_BYTES;
        const int kk = kt * BK;
        #pragma unroll
        for (int i = 0; i < 2; i++) {
            int c_lin = tid + i * THREADS;
            int row = c_lin >> 3, c = c_lin & 7;
            cp16(sB + (uint32_t)row * 128 + (uint32_t)((c ^ (row & 7)) << 4),
                 wq + (size_t)(n0 + row) * K_DIM + kk + c * 8);
        }
    };

    // A: LDG 8 float4 into regs
    float4 areg[8];
    auto load_A = [&](int kt) {
        const float* g = agp_base + kt * BK;
        #pragma unroll
        for (int j = 0; j < 8; j++)
            areg[j] = *reinterpret_cast<const float4*>(g + j * 4);
    };
    // cvt + STS into stage s
    auto store_A = [&](int s) {
        const uint32_t sA = sb + s * STAGE_BYTES;
        #pragma unroll
        for (int t = 0; t < 4; t++) {
            const float4 v0 = areg[2 * t];
            const float4 v1 = areg[2 * t + 1];
            sts128(sA + asts[t],
                   pack_h2(v0.x, v0.y), pack_h2(v0.z, v0.w),
                   pack_h2(v1.x, v1.y), pack_h2(v1.z, v1.w));
        }
    };

    // ---- ldmatrix per-lane base addresses (same as R9) ----
    const int lt = lane >> 3;
    const int lr = lane & 7;
    uint32_t baseA[2], baseB[2];
    {
        const int rowoffA = (lt & 1) * 8;
        const int khA = lt >> 1;
        #pragma unroll
        for (int tm = 0; tm < 2; tm++) {
            int row = warp_m + tm * 16 + rowoffA + lr;
            baseA[tm] = (uint32_t)row * 128 + (uint32_t)((khA ^ lr) << 4);
        }
        const int rowoffB = (lt >> 1) * 8;
        const int khB = lt & 1;
        #pragma unroll
        for (int tnp = 0; tnp < 2; tnp++) {
            int row = warp_n + tnp * 16 + rowoffB + lr;
            baseB[tnp] = (uint32_t)A_STAGE_BYTES +
                         (uint32_t)row * 128 + (uint32_t)((khB ^ lr) << 4);
        }
    }

    float acc[2][4][4];
    #pragma unroll
    for (int i = 0; i < 2; i++)
        #pragma unroll
        for (int j = 0; j < 4; j++)
            #pragma unroll
            for (int r = 0; r < 4; r++) acc[i][j][r] = 0.0f;

    // ---- prologue: stage 0 ----
    load_A(0);
    load_B(0, 0);
    cp_commit();
    store_A(0);
    cp_wait0();
    __syncthreads();

    for (int kt = 0; kt < KT; kt++) {
        if (kt + 1 < KT) {
            load_A(kt + 1);            // LDG early, consumed at iter bottom
            load_B((kt + 1) & 1, kt + 1);
            cp_commit();
        }

        const uint32_t sStage = sb + (uint32_t)(kt & 1) * STAGE_BYTES;
        const uint32_t a0base = sStage + baseA[0];
        const uint32_t a1base = sStage + baseA[1];
        const uint32_t b0base = sStage + baseB[0];
        const uint32_t b1base = sStage + baseB[1];

        #pragma unroll
        for (int ks = 0; ks < 4; ks++) {
            const uint32_t kx = (uint32_t)ks << 5;
            uint32_t a[2][4];
            ldsm_x4(a[0][0], a[0][1], a[0][2], a[0][3], a0base ^ kx);
            ldsm_x4(a[1][0], a[1][1], a[1][2], a[1][3], a1base ^ kx);
            uint32_t b[4][2];
            ldsm_x4(b[0][0], b[0][1], b[1][0], b[1][1], b0base ^ kx);
            ldsm_x4(b[2][0], b[2][1], b[3][0], b[3][1], b1base ^ kx);
            #pragma unroll
            for (int tm = 0; tm < 2; tm++)
                #pragma unroll
                for (int tn = 0; tn < 4; tn++)
                    mma_f16(acc[tm][tn], a[tm][0], a[tm][1], a[tm][2], a[tm][3],
                            b[tn][0], b[tn][1]);
        }

        if (kt + 1 < KT) {
            store_A((kt + 1) & 1);     // buf was last read in iter kt-1 (fenced)
            cp_wait0();
            __syncthreads();           // publish A STS + B cp.async for kt+1
        }
    }

    // ---- Epilogue: out = scale*acc + bias ----
    const float scale = d_scale;
    #pragma unroll
    for (int tm = 0; tm < 2; tm++) {
        #pragma unroll
        for (int tn = 0; tn < 4; tn++) {
            const int row = m0 + warp_m + tm * 16 + grp;
            const int col = n0 + warp_n + tn * 8 + qc * 2;
            const float2 bv = *reinterpret_cast<const float2*>(bias + col);
            float2 v0, v1;
            v0.x = fmaf(scale, acc[tm][tn][0], bv.x);
            v0.y = fmaf(scale, acc[tm][tn][1], bv.y);
            v1.x = fmaf(scale, acc[tm][tn][2], bv.x);
            v1.y = fmaf(scale, acc[tm][tn][3], bv.y);
            *reinterpret_cast<float2*>(out + (size_t)row * N_DIM + col) = v0;
            *reinterpret_cast<float2*>(out + (size_t)(row + 8) * N_DIM + col) = v1;
        }
    }
}

// ============================================================================
// Host
// ============================================================================
extern "C" void kernel_launch(void* const* d_in, const int* in_sizes, int n_in,
                              void* d_out, int out_size) {
    const float* x    = (const float*)d_in[0];
    const float* w    = (const float*)d_in[1];
    const float* bias = (const float*)d_in[2];
    float* out        = (float*)d_out;
    const int M = in_sizes[0] / K_DIM;   // 65536

    cudaFuncSetAttribute(gemm_f16, cudaFuncAttributeMaxDynamicSharedMemorySize,
                         SMEM_TOTAL);

    k_abssum<<<256, 256>>>(w);
    k_scale<<<1, 1>>>();
    k_quant<<<(N_DIM * K_DIM) / 256, 256>>>(w);

    const int grid = (M / BM) * (N_DIM / BN);   // 4096
    gemm_f16<<<grid, THREADS, SMEM_TOTAL>>>(x, bias, out);
}

// round 11
// speedup vs baseline: 2.1680x; 2.1680x over previous
#include <cuda_runtime.h>
#include <cuda_fp16.h>
#include <cstdint>

// ============================================================================
// QuantizedLinear: out = scale * (x @ S^T) + bias, S = sign(w)*(|w|>0.7*mean|w|)
// x [65536, 512] fp32, w [512, 512] fp32, bias [512] fp32, out [65536, 512] fp32
//
// R11: fused x->fp16 conversion in the GEMM A-path, with COALESCED LDG
// (R10's regression was 16-rows-per-warp LDG scatter -> L1 wavefront storm).
// A: LDG.128 row-major coalesced -> cvt.rn.f16x2 -> STS.64 (SW128)
// B: cp.async fp16 ternary (SW128). ldmatrix.x4 + mma.sync.m16n8k16.f16.
// ============================================================================
#define K_DIM 512
#define N_DIM 512
#define BM 128
#define BN 64
#define BK 64
#define KT (K_DIM / BK)      // 8
#define THREADS 256

#define A_STAGE_BYTES (BM * BK * 2)                    // 16384 (128B rows, SW128)
#define B_STAGE_BYTES (BN * BK * 2)                    // 8192
#define STAGE_BYTES   (A_STAGE_BYTES + B_STAGE_BYTES)  // 24576
#define SMEM_TOTAL    (2 * STAGE_BYTES + 128)          // 49280

// Scratch (allocation-free __device__ globals)
__device__ __half  d_wq[N_DIM * K_DIM];
__device__ double  d_partial[256];
__device__ float   d_scale;
__device__ float   d_thresh;

// ============================================================================
// Prep kernels
// ============================================================================
__global__ void k_abssum(const float* __restrict__ w) {
    __shared__ double s[256];
    int b = blockIdx.x, t = threadIdx.x;
    const float* p = w + b * 1024;
    double acc = (double)fabsf(p[t]) + (double)fabsf(p[t + 256]) +
                 (double)fabsf(p[t + 512]) + (double)fabsf(p[t + 768]);
    s[t] = acc;
    __syncthreads();
    for (int o = 128; o > 0; o >>= 1) {
        if (t < o) s[t] += s[t + o];
        __syncthreads();
    }
    if (t == 0) d_partial[b] = s[0];
}

__global__ void k_scale() {
    double tot = 0.0;
    for (int i = 0; i < 256; i++) tot += d_partial[i];
    float sc = (float)(tot / (double)(N_DIM * K_DIM));
    if (sc < 1e-8f) sc = 1e-8f;
    d_scale = sc;
    d_thresh = 0.7f * sc;
}

__global__ void k_quant(const float* __restrict__ w) {
    int i = blockIdx.x * blockDim.x + threadIdx.x;
    float v = w[i];
    float th = d_thresh;
    float q = (fabsf(v) > th) ? (v > 0.0f ? 1.0f : -1.0f) : 0.0f;
    d_wq[i] = __float2half_rn(q);    // exact in fp16
}

// ============================================================================
// Helpers
// ============================================================================
__device__ __forceinline__ uint32_t smem_u32(const void* p) {
    uint32_t a;
    asm("{ .reg .u64 t; cvta.to.shared.u64 t, %1; cvt.u32.u64 %0, t; }"
        : "=r"(a) : "l"(p));
    return a;
}

__device__ __forceinline__ void cp16(uint32_t saddr, const void* gaddr) {
    asm volatile("cp.async.cg.shared.global [%0], [%1], 16;"
                 :: "r"(saddr), "l"(gaddr) : "memory");
}

__device__ __forceinline__ void cp_commit() {
    asm volatile("cp.async.commit_group;" ::: "memory");
}

__device__ __forceinline__ void cp_wait0() {
    asm volatile("cp.async.wait_group 0;" ::: "memory");
}

__device__ __forceinline__ uint32_t pack_h2(float lo, float hi) {
    uint32_t r;
    asm("cvt.rn.f16x2.f32 %0, %1, %2;" : "=r"(r) : "f"(hi), "f"(lo));
    return r;
}

__device__ __forceinline__ void sts64(uint32_t addr, uint32_t r0, uint32_t r1) {
    asm volatile("st.shared.v2.b32 [%0], {%1,%2};"
                 :: "r"(addr), "r"(r0), "r"(r1) : "memory");
}

__device__ __forceinline__ void ldsm_x4(uint32_t& r0, uint32_t& r1,
                                        uint32_t& r2, uint32_t& r3,
                                        uint32_t addr) {
    asm volatile("ldmatrix.sync.aligned.m8n8.x4.shared.b16 {%0,%1,%2,%3}, [%4];"
                 : "=r"(r0), "=r"(r1), "=r"(r2), "=r"(r3) : "r"(addr));
}

__device__ __forceinline__ void mma_f16(float* c, uint32_t a0, uint32_t a1,
                                        uint32_t a2, uint32_t a3,
                                        uint32_t b0, uint32_t b1) {
    asm volatile(
        "mma.sync.aligned.m16n8k16.row.col.f32.f16.f16.f32 "
        "{%0,%1,%2,%3}, {%4,%5,%6,%7}, {%8,%9}, {%0,%1,%2,%3};"
        : "+f"(c[0]), "+f"(c[1]), "+f"(c[2]), "+f"(c[3])
        : "r"(a0), "r"(a1), "r"(a2), "r"(a3), "r"(b0), "r"(b1));
}

// ============================================================================
// Main GEMM: block 128x64, 8 warps (4M x 2N), warp tile 32x32
// A: coalesced LDG.128 fp32 + cvt + STS.64 fp16 (SW128), double-buffered
// B: cp.async fp16 (SW128). SW128: chunk c at position c ^ (row & 7).
// ============================================================================
__global__ void __launch_bounds__(THREADS, 2) gemm_f16(
    const float* __restrict__ x,
    const float* __restrict__ bias,
    float* __restrict__ out)
{
    extern __shared__ char smem[];
    const uint32_t sb = (smem_u32(smem) + 127u) & ~127u;
    const int tid = threadIdx.x;
    const int wid = tid >> 5;
    const int lane = tid & 31;
    const int grp = lane >> 2;
    const int qc = lane & 3;

    const int ntile = blockIdx.x & 7;       // consecutive bids share M-tile
    const int mtile = blockIdx.x >> 3;
    const int m0 = mtile * BM;
    const int n0 = ntile * BN;

    const int warp_m = (wid & 3) * 32;
    const int warp_n = (wid >> 2) * 32;

    const __half* wq = d_wq;

    // ---- A staging (coalesced): thread -> fp32 chunk c of rows r0+16i ----
    // c = tid & 15 (16B fp32 chunk within 256B row), r0 = tid >> 4, i = 0..7.
    const int ac = tid & 15;
    const int ar0 = tid >> 4;
    const float* agp = x + (size_t)(m0 + ar0) * K_DIM + ac * 4;  // + kt*BK later
    // STS.64: fp16 group g = ac>>1, sub-half = ac&1; XOR term constant (r0&7).
    const uint32_t asts0 = (uint32_t)ar0 * 128 +
                           (uint32_t)((((ac >> 1) ^ (ar0 & 7)) << 4) +
                                      ((ac & 1) << 3));
    // per-i strides: global 16*K_DIM floats, smem 16*128 bytes.

    // ---- B loader: 512 chunks / 256 threads = 2 per thread ----
    auto load_B = [&](int s, int kt) {
        const uint32_t sB = sb + s * STAGE_BYTES + A_STAGE_BYTES;
        const int kk = kt * BK;
        #pragma unroll
        for (int i = 0; i < 2; i++) {
            int c_lin = tid + i * THREADS;
            int row = c_lin >> 3, c = c_lin & 7;
            cp16(sB + (uint32_t)row * 128 + (uint32_t)((c ^ (row & 7)) << 4),
                 wq + (size_t)(n0 + row) * K_DIM + kk + c * 8);
        }
    };

    float4 areg[8];
    auto load_A = [&](int kt) {
        const float* g = agp + kt * BK;
        #pragma unroll
        for (int i = 0; i < 8; i++)
            areg[i] = *reinterpret_cast<const float4*>(g + (size_t)i * 16 * K_DIM);
    };
    auto store_A = [&](int s) {
        const uint32_t sA = sb + s * STAGE_BYTES + asts0;
        #pragma unroll
        for (int i = 0; i < 8; i++) {
            const float4 v = areg[i];
            sts64(sA + (uint32_t)i * (16 * 128),
                  pack_h2(v.x, v.y), pack_h2(v.z, v.w));
        }
    };

    // ---- ldmatrix per-lane base addresses ----
    const int lt = lane >> 3;
    const int lr = lane & 7;
    uint32_t baseA[2], baseB[2];
    {
        const int rowoffA = (lt & 1) * 8;
        const int khA = lt >> 1;
        #pragma unroll
        for (int tm = 0; tm < 2; tm++) {
            int row = warp_m + tm * 16 + rowoffA + lr;
            baseA[tm] = (uint32_t)row * 128 + (uint32_t)((khA ^ lr) << 4);
        }
        const int rowoffB = (lt >> 1) * 8;
        const int khB = lt & 1;
        #pragma unroll
        for (int tnp = 0; tnp < 2; tnp++) {
            int row = warp_n + tnp * 16 + rowoffB + lr;
            baseB[tnp] = (uint32_t)A_STAGE_BYTES +
                         (uint32_t)row * 128 + (uint32_t)((khB ^ lr) << 4);
        }
    }

    float acc[2][4][4];
    #pragma unroll
    for (int i = 0; i < 2; i++)
        #pragma unroll
        for (int j = 0; j < 4; j++)
            #pragma unroll
            for (int r = 0; r < 4; r++) acc[i][j][r] = 0.0f;

    // ---- prologue: stage 0 ----
    load_A(0);
    load_B(0, 0);
    cp_commit();
    store_A(0);
    cp_wait0();
    __syncthreads();

    for (int kt = 0; kt < KT; kt++) {
        if (kt + 1 < KT) {
            load_A(kt + 1);            // coalesced LDG, consumed at iter bottom
            load_B((kt + 1) & 1, kt + 1);
            cp_commit();
        }

        const uint32_t sStage = sb + (uint32_t)(kt & 1) * STAGE_BYTES;
        const uint32_t a0base = sStage + baseA[0];
        const uint32_t a1base = sStage + baseA[1];
        const uint32_t b0base = sStage + baseB[0];
        const uint32_t b1base = sStage + baseB[1];

        #pragma unroll
        for (int ks = 0; ks < 4; ks++) {
            const uint32_t kx = (uint32_t)ks << 5;
            uint32_t a[2][4];
            ldsm_x4(a[0][0], a[0][1], a[0][2], a[0][3], a0base ^ kx);
            ldsm_x4(a[1][0], a[1][1], a[1][2], a[1][3], a1base ^ kx);
            uint32_t b[4][2];
            ldsm_x4(b[0][0], b[0][1], b[1][0], b[1][1], b0base ^ kx);
            ldsm_x4(b[2][0], b[2][1], b[3][0], b[3][1], b1base ^ kx);
            #pragma unroll
            for (int tm = 0; tm < 2; tm++)
                #pragma unroll
                for (int tn = 0; tn < 4; tn++)
                    mma_f16(acc[tm][tn], a[tm][0], a[tm][1], a[tm][2], a[tm][3],
                            b[tn][0], b[tn][1]);
        }

        if (kt + 1 < KT) {
            store_A((kt + 1) & 1);     // buffer last read in iter kt-1 (fenced)
            cp_wait0();
            __syncthreads();           // publish A STS + B cp.async for kt+1
        }
    }

    // ---- Epilogue: out = scale*acc + bias ----
    const float scale = d_scale;
    #pragma unroll
    for (int tm = 0; tm < 2; tm++) {
        #pragma unroll
        for (int tn = 0; tn < 4; tn++) {
            const int row = m0 + warp_m + tm * 16 + grp;
            const int col = n0 + warp_n + tn * 8 + qc * 2;
            const float2 bv = *reinterpret_cast<const float2*>(bias + col);
            float2 v0, v1;
            v0.x = fmaf(scale, acc[tm][tn][0], bv.x);
            v0.y = fmaf(scale, acc[tm][tn][1], bv.y);
            v1.x = fmaf(scale, acc[tm][tn][2], bv.x);
            v1.y = fmaf(scale, acc[tm][tn][3], bv.y);
            *reinterpret_cast<float2*>(out + (size_t)row * N_DIM + col) = v0;
            *reinterpret_cast<float2*>(out + (size_t)(row + 8) * N_DIM + col) = v1;
        }
    }
}

// ============================================================================
// Host
// ============================================================================
extern "C" void kernel_launch(void* const* d_in, const int* in_sizes, int n_in,
                              void* d_out, int out_size) {
    const float* x    = (const float*)d_in[0];
    const float* w    = (const float*)d_in[1];
    const float* bias = (const float*)d_in[2];
    float* out        = (float*)d_out;
    const int M = in_sizes[0] / K_DIM;   // 65536

    cudaFuncSetAttribute(gemm_f16, cudaFuncAttributeMaxDynamicSharedMemorySize,
                         SMEM_TOTAL);

    k_abssum<<<256, 256>>>(w);
    k_scale<<<1, 1>>>();
    k_quant<<<(N_DIM * K_DIM) / 256, 256>>>(w);

    const int grid = (M / BM) * (N_DIM / BN);   // 4096
    gemm_f16<<<grid, THREADS, SMEM_TOTAL>>>(x, bias, out);
}